// round 12
// baseline (speedup 1.0000x reference)
#include <cuda_runtime.h>
#include <math.h>
#include <float.h>

#define NN 50000
#define EE 400000
#define E2T (EE + NN)
#define ND 128
#define ED 64
#define HID 128
#define GIN 258
#define CIN 320

typedef unsigned long long ull;

// ---------------- packed f32x2 helpers ----------------
__device__ __forceinline__ ull pk2(float lo, float hi) {
    ull r; asm("mov.b64 %0,{%1,%2};" : "=l"(r) : "f"(lo), "f"(hi)); return r;
}
__device__ __forceinline__ ull dup2(float v) { return pk2(v, v); }
__device__ __forceinline__ void upk2(ull p, float& lo, float& hi) {
    asm("mov.b64 {%0,%1},%2;" : "=f"(lo), "=f"(hi) : "l"(p));
}
__device__ __forceinline__ ull ffma2(ull a, ull b, ull c) {
    ull d; asm("fma.rn.f32x2 %0,%1,%2,%3;" : "=l"(d) : "l"(a), "l"(b), "l"(c)); return d;
}

// ---------------- scratch ----------------
__device__ float g_xsum_out[NN * ND];
__device__ float g_xsum_in [NN * ND];
__device__ int   g_deg_out [NN];
__device__ int   g_deg_in  [NN];
__device__ float g_loop    [NN * ED];
__device__ float g_xi      [NN * GIN];
__device__ float g_xlr1    [(size_t)NN * 512];
__device__ float g_xlr2    [NN * 256];
__device__ float g_pre12   [NN * 256];
__device__ float g_wpack   [258 * 512];
__device__ float g_logit1  [E2T * 2];
__device__ float g_h1      [NN * HID];
__device__ float g_logit2  [E2T];
__device__ float g_h2      [NN * HID];
__device__ int   g_rowptr  [NN + 1];
__device__ int   g_cursor  [NN];
__device__ int   g_psrc    [E2T];
__device__ int   g_ipos    [E2T];
__device__ float g_ew      [(size_t)E2T * 256];

// ---------------- stage 1+2 fused: embed + scatter + degrees + loop sums -------------
__global__ void k_embed_scatter(const int* __restrict__ src, const int* __restrict__ dst,
                                const float* __restrict__ ea,
                                const float* __restrict__ epw, const float* __restrict__ epb,
                                float* __restrict__ xsum_out, float* __restrict__ xsum_in,
                                int* __restrict__ deg_out, int* __restrict__ deg_in,
                                float* __restrict__ loop) {
    __shared__ float4 wsh[ED * 32];
    __shared__ float4 bsh4[32];
    __shared__ float  easm[16][ED];
    int tid = threadIdx.x;
    for (int i = tid; i < ED * 32; i += 256) wsh[i] = ((const float4*)epw)[i];
    if (tid < 32) bsh4[tid] = ((const float4*)epb)[tid];
    __syncthreads();
    const ulonglong2* wsh2 = (const ulonglong2*)wsh;
    int sub = tid >> 5;
    int q   = tid & 31;
    for (int base = blockIdx.x * 16; base < EE; base += gridDim.x * 16) {
        #pragma unroll
        for (int r = 0; r < 4; r++) {
            int idx = tid + r * 256;
            int ee = base + (idx >> 6);
            if (ee < EE) easm[idx >> 6][idx & 63] = ea[(size_t)ee * ED + (idx & 63)];
        }
        __syncthreads();
        {
            int e_loc = tid >> 4, q2 = tid & 15;
            int e = base + e_loc;
            if (e < EE) {
                int d = dst[e];
                if (q2 == 0) {
                    atomicAdd(&deg_in[d], 1);
                    atomicAdd(&deg_out[src[e]], 1);
                }
                float4 v = ((const float4*)easm[e_loc])[q2];
                atomicAdd((float4*)(loop + (size_t)d * ED + q2 * 4), v);
            }
        }
        int e0 = base + sub, e1 = base + sub + 8;
        float4 bb = bsh4[q];
        ull a0[2] = { pk2(bb.x, bb.y), pk2(bb.z, bb.w) };
        ull a1[2] = { a0[0], a0[1] };
        const float* er0 = easm[sub];
        const float* er1 = easm[sub + 8];
        #pragma unroll
        for (int k = 0; k < ED; k++) {
            ulonglong2 w2 = wsh2[k * 32 + q];
            ull b0 = dup2(er0[k]), b1 = dup2(er1[k]);
            a0[0] = ffma2(b0, w2.x, a0[0]); a0[1] = ffma2(b0, w2.y, a0[1]);
            a1[0] = ffma2(b1, w2.x, a1[0]); a1[1] = ffma2(b1, w2.y, a1[1]);
        }
        if (e0 < EE) {
            float4 o; upk2(a0[0], o.x, o.y); upk2(a0[1], o.z, o.w);
            o.x = fmaxf(o.x, 0.f); o.y = fmaxf(o.y, 0.f); o.z = fmaxf(o.z, 0.f); o.w = fmaxf(o.w, 0.f);
            int s = src[e0], d = dst[e0];
            atomicAdd((float4*)(xsum_out + (size_t)s * ND + q * 4), o);
            atomicAdd((float4*)(xsum_in  + (size_t)d * ND + q * 4), o);
        }
        if (e1 < EE) {
            float4 o; upk2(a1[0], o.x, o.y); upk2(a1[1], o.z, o.w);
            o.x = fmaxf(o.x, 0.f); o.y = fmaxf(o.y, 0.f); o.z = fmaxf(o.z, 0.f); o.w = fmaxf(o.w, 0.f);
            int s = src[e1], d = dst[e1];
            atomicAdd((float4*)(xsum_out + (size_t)s * ND + q * 4), o);
            atomicAdd((float4*)(xsum_in  + (size_t)d * ND + q * 4), o);
        }
        __syncthreads();
    }
}

// ---------------- stage 3: build xi, finalize loop_attr ----------------
__global__ void k_build_xi(const float* __restrict__ node_stats,
                           const float* __restrict__ xsum_out, const float* __restrict__ xsum_in,
                           const int* __restrict__ deg_out, const int* __restrict__ deg_in,
                           float* __restrict__ xi) {
    int tid = blockIdx.x * blockDim.x + threadIdx.x;
    if (tid >= NN * GIN) return;
    int i = tid / GIN, j = tid - i * GIN;
    float v;
    if (j < 128)      v = xsum_out[i * 128 + j]        / fmaxf((float)deg_out[i], 1.f);
    else if (j < 256) v = xsum_in [i * 128 + (j - 128)] / fmaxf((float)deg_in [i], 1.f);
    else              v = node_stats[i * 2 + (j - 256)];
    xi[tid] = v;
}

__global__ void k_loop_div(float* __restrict__ loop, const int* __restrict__ deg_in) {
    int tid = blockIdx.x * blockDim.x + threadIdx.x;
    if (tid >= NN * ED) return;
    int i = tid >> 6;
    loop[tid] = loop[tid] / fmaxf((float)deg_in[i], 1.f);
}

// ---------------- CSR prefix scan ----------------
__global__ void k_prefix(const int* __restrict__ deg_in, int* __restrict__ rowptr,
                         int* __restrict__ cursor) {
    __shared__ int wsums[32];
    __shared__ int carry_s;
    int t = threadIdx.x, lane = t & 31, wid = t >> 5;
    if (t == 0) carry_s = 0;
    __syncthreads();
    for (int base = 0; base < NN; base += 1024) {
        int n = base + t;
        int v = (n < NN) ? deg_in[n] + 1 : 0;
        int x = v;
        #pragma unroll
        for (int o = 1; o < 32; o <<= 1) {
            int y = __shfl_up_sync(0xffffffffu, x, o);
            if (lane >= o) x += y;
        }
        if (lane == 31) wsums[wid] = x;
        __syncthreads();
        if (wid == 0) {
            int s = wsums[lane];
            #pragma unroll
            for (int o = 1; o < 32; o <<= 1) {
                int y = __shfl_up_sync(0xffffffffu, s, o);
                if (lane >= o) s += y;
            }
            wsums[lane] = s;
        }
        __syncthreads();
        int excl = x - v + (wid > 0 ? wsums[wid - 1] : 0) + carry_s;
        if (n < NN) { rowptr[n] = excl; cursor[n] = excl; }
        __syncthreads();
        if (t == 0) carry_s += wsums[31];
        __syncthreads();
    }
    if (t == 0) rowptr[NN] = E2T;
}

__global__ void k_perm(const int* __restrict__ src, const int* __restrict__ dst,
                       int* __restrict__ cursor, int* __restrict__ psrc,
                       int* __restrict__ ipos) {
    int e = blockIdx.x * blockDim.x + threadIdx.x;
    if (e < EE) {
        int pos = atomicAdd(&cursor[dst[e]], 1);
        psrc[pos] = src[e];
        ipos[e] = pos;
    } else if (e < E2T) {
        int i = e - EE;
        int pos = atomicAdd(&cursor[i], 1);
        psrc[pos] = i;
        ipos[e] = pos;
    }
}

// ---------------- weight pack: C[k][0:N1]=B1, C[k][N1:N1+N2]=B2 ----------------
__global__ void k_pack2(const float* __restrict__ B1, const float* __restrict__ B2,
                        float* __restrict__ C, int K, int N1, int N2) {
    int i = blockIdx.x * 256 + threadIdx.x;
    int N = N1 + N2;
    if (i >= K * N) return;
    int k = i / N, c = i - k * N;
    C[i] = (c < N1) ? B1[k * N1 + c] : B2[k * N2 + (c - N1)];
}

// ---------------- fp32 tiled GEMM with FFMA2: 128x128 tile, 8x8/thread --------------
#define BM 128
#define BN 128
#define BKK 16
__global__ void __launch_bounds__(256)
k_gemm(const float* __restrict__ A, const float* __restrict__ B,
       float* __restrict__ C, int M, int K, int Nc) {
    __shared__ float As[BKK][BM + 4];
    __shared__ float Bs[BKK][BN + 4];
    int brow = blockIdx.y * BM, bcol = blockIdx.x * BN;
    int tid = threadIdx.x;
    int tr = tid >> 4, tc = tid & 15;
    ull acc[8][4];
    #pragma unroll
    for (int i = 0; i < 8; i++)
        #pragma unroll
        for (int j = 0; j < 4; j++) acc[i][j] = 0ull;
    for (int k0 = 0; k0 < K; k0 += BKK) {
        // A tile: 128 rows x 16 cols, float2 loads (K always even)
        #pragma unroll
        for (int it = 0; it < 4; it++) {
            int idx = tid + it * 256;
            int r = idx >> 3, c2 = idx & 7;
            int gr = brow + r, gc = k0 + c2 * 2;
            float2 v = make_float2(0.f, 0.f);
            if (gr < M) {
                if (gc + 1 < K)  v = *(const float2*)&A[(size_t)gr * K + gc];
                else if (gc < K) v.x = A[(size_t)gr * K + gc];
            }
            As[c2 * 2][r] = v.x;
            As[c2 * 2 + 1][r] = v.y;
        }
        // B tile: 16 rows x 128 cols, float4 loads (Nc mult of 4, bcol mult of 128)
        #pragma unroll
        for (int it = 0; it < 2; it++) {
            int idx = tid + it * 256;
            int r = idx >> 5, c4 = idx & 31;
            int gr = k0 + r;
            float4 v = make_float4(0.f, 0.f, 0.f, 0.f);
            if (gr < K) v = *(const float4*)&B[(size_t)gr * Nc + bcol + c4 * 4];
            *(float4*)&Bs[r][c4 * 4] = v;
        }
        __syncthreads();
        #pragma unroll
        for (int kk = 0; kk < BKK; kk++) {
            float4 a0 = *(const float4*)&As[kk][tr * 8];
            float4 a1 = *(const float4*)&As[kk][tr * 8 + 4];
            ulonglong2 b0 = *(const ulonglong2*)&Bs[kk][tc * 8];
            ulonglong2 b1 = *(const ulonglong2*)&Bs[kk][tc * 8 + 4];
            ull d;
            d = dup2(a0.x); acc[0][0]=ffma2(d,b0.x,acc[0][0]); acc[0][1]=ffma2(d,b0.y,acc[0][1]); acc[0][2]=ffma2(d,b1.x,acc[0][2]); acc[0][3]=ffma2(d,b1.y,acc[0][3]);
            d = dup2(a0.y); acc[1][0]=ffma2(d,b0.x,acc[1][0]); acc[1][1]=ffma2(d,b0.y,acc[1][1]); acc[1][2]=ffma2(d,b1.x,acc[1][2]); acc[1][3]=ffma2(d,b1.y,acc[1][3]);
            d = dup2(a0.z); acc[2][0]=ffma2(d,b0.x,acc[2][0]); acc[2][1]=ffma2(d,b0.y,acc[2][1]); acc[2][2]=ffma2(d,b1.x,acc[2][2]); acc[2][3]=ffma2(d,b1.y,acc[2][3]);
            d = dup2(a0.w); acc[3][0]=ffma2(d,b0.x,acc[3][0]); acc[3][1]=ffma2(d,b0.y,acc[3][1]); acc[3][2]=ffma2(d,b1.x,acc[3][2]); acc[3][3]=ffma2(d,b1.y,acc[3][3]);
            d = dup2(a1.x); acc[4][0]=ffma2(d,b0.x,acc[4][0]); acc[4][1]=ffma2(d,b0.y,acc[4][1]); acc[4][2]=ffma2(d,b1.x,acc[4][2]); acc[4][3]=ffma2(d,b1.y,acc[4][3]);
            d = dup2(a1.y); acc[5][0]=ffma2(d,b0.x,acc[5][0]); acc[5][1]=ffma2(d,b0.y,acc[5][1]); acc[5][2]=ffma2(d,b1.x,acc[5][2]); acc[5][3]=ffma2(d,b1.y,acc[5][3]);
            d = dup2(a1.z); acc[6][0]=ffma2(d,b0.x,acc[6][0]); acc[6][1]=ffma2(d,b0.y,acc[6][1]); acc[6][2]=ffma2(d,b1.x,acc[6][2]); acc[6][3]=ffma2(d,b1.y,acc[6][3]);
            d = dup2(a1.w); acc[7][0]=ffma2(d,b0.x,acc[7][0]); acc[7][1]=ffma2(d,b0.y,acc[7][1]); acc[7][2]=ffma2(d,b1.x,acc[7][2]); acc[7][3]=ffma2(d,b1.y,acc[7][3]);
        }
        __syncthreads();
    }
    #pragma unroll
    for (int i = 0; i < 8; i++) {
        int row = brow + tr * 8 + i;
        if (row >= M) continue;
        float v[8];
        upk2(acc[i][0], v[0], v[1]); upk2(acc[i][1], v[2], v[3]);
        upk2(acc[i][2], v[4], v[5]); upk2(acc[i][3], v[6], v[7]);
        #pragma unroll
        for (int j = 0; j < 8; j++) {
            int col = bcol + tc * 8 + j;
            if (col < Nc) C[(size_t)row * Nc + col] = v[j];
        }
    }
}

// ---------------- logits add pass: warp per edge; xl/xr packed in one buffer ----------
// row s: xlr[s*STRIDE .. +OUT) = xl, xlr[d*STRIDE + OUT ..) = xr
template <int OUT, int H, int STRIDE>
__global__ void __launch_bounds__(256)
k_logit_add(const float* __restrict__ xlr, const float* __restrict__ ew,
            const float* __restrict__ att,
            const int* __restrict__ src, const int* __restrict__ dst,
            const int* __restrict__ ipos, float* __restrict__ logit) {
    int gw = (blockIdx.x * 256 + threadIdx.x) >> 5;
    int lane = threadIdx.x & 31;
    if (gw >= E2T) return;
    int e = gw;
    int s, d;
    if (e < EE) { s = src[e]; d = dst[e]; } else { s = d = e - EE; }
    const float* xls = xlr + (size_t)s * STRIDE;
    const float* xrd = xlr + (size_t)d * STRIDE + OUT;
    const float* ewe = ew + (size_t)e * OUT;
    float4 a0 = *(const float4*)(xls + lane * 4);
    float4 b0 = *(const float4*)(xrd + lane * 4);
    float4 c0 = *(const float4*)(ewe + lane * 4);
    float4 t0 = *(const float4*)(att + lane * 4);
    float v0, p0 = 0.f;
    v0 = a0.x + b0.x + c0.x; v0 = v0 > 0.f ? v0 : 0.2f * v0; p0 = fmaf(v0, t0.x, p0);
    v0 = a0.y + b0.y + c0.y; v0 = v0 > 0.f ? v0 : 0.2f * v0; p0 = fmaf(v0, t0.y, p0);
    v0 = a0.z + b0.z + c0.z; v0 = v0 > 0.f ? v0 : 0.2f * v0; p0 = fmaf(v0, t0.z, p0);
    v0 = a0.w + b0.w + c0.w; v0 = v0 > 0.f ? v0 : 0.2f * v0; p0 = fmaf(v0, t0.w, p0);
    float p1 = 0.f;
    if (H == 2) {
        float4 a1 = *(const float4*)(xls + 128 + lane * 4);
        float4 b1 = *(const float4*)(xrd + 128 + lane * 4);
        float4 c1 = *(const float4*)(ewe + 128 + lane * 4);
        float4 t1 = *(const float4*)(att + 128 + lane * 4);
        float v1;
        v1 = a1.x + b1.x + c1.x; v1 = v1 > 0.f ? v1 : 0.2f * v1; p1 = fmaf(v1, t1.x, p1);
        v1 = a1.y + b1.y + c1.y; v1 = v1 > 0.f ? v1 : 0.2f * v1; p1 = fmaf(v1, t1.y, p1);
        v1 = a1.z + b1.z + c1.z; v1 = v1 > 0.f ? v1 : 0.2f * v1; p1 = fmaf(v1, t1.z, p1);
        v1 = a1.w + b1.w + c1.w; v1 = v1 > 0.f ? v1 : 0.2f * v1; p1 = fmaf(v1, t1.w, p1);
    }
    #pragma unroll
    for (int o = 16; o; o >>= 1) {
        p0 += __shfl_xor_sync(0xffffffffu, p0, o);
        if (H == 2) p1 += __shfl_xor_sync(0xffffffffu, p1, o);
    }
    if (lane == 0) {
        int pos = ipos[e];
        if (H == 2) { logit[(size_t)pos * 2] = p0; logit[(size_t)pos * 2 + 1] = p1; }
        else        logit[pos] = p0;
    }
}

// ---------------- GATv2 fused reduce ----------------
template <int OUT, int H, int STRIDE>
__global__ void __launch_bounds__(256)
k_gat_reduce(const float* __restrict__ xl, const float* __restrict__ slog,
             const int* __restrict__ rowptr, const int* __restrict__ psrc,
             const float* __restrict__ bias, const float* __restrict__ gg,
             const float* __restrict__ bb, float* __restrict__ out) {
    const int R = OUT / 32;
    __shared__ float csm[8][32 * H];
    __shared__ int   ssm2[8][32];
    int warp = threadIdx.x >> 5, lane = threadIdx.x & 31;
    int node = blockIdx.x * 8 + warp;
    if (node >= NN) return;
    int r0 = rowptr[node], r1 = rowptr[node + 1], cnt = r1 - r0;
    float mx[H];
    #pragma unroll
    for (int h = 0; h < H; h++) mx[h] = -FLT_MAX;
    for (int j = lane; j < cnt; j += 32) {
        #pragma unroll
        for (int h = 0; h < H; h++) mx[h] = fmaxf(mx[h], slog[(size_t)(r0 + j) * H + h]);
    }
    #pragma unroll
    for (int h = 0; h < H; h++)
        #pragma unroll
        for (int o = 16; o; o >>= 1) mx[h] = fmaxf(mx[h], __shfl_xor_sync(0xffffffffu, mx[h], o));
    float den[H];
    #pragma unroll
    for (int h = 0; h < H; h++) den[h] = 0.f;
    for (int j = lane; j < cnt; j += 32) {
        #pragma unroll
        for (int h = 0; h < H; h++) den[h] += expf(slog[(size_t)(r0 + j) * H + h] - mx[h]);
    }
    float inv[H];
    #pragma unroll
    for (int h = 0; h < H; h++) {
        #pragma unroll
        for (int o = 16; o; o >>= 1) den[h] += __shfl_xor_sync(0xffffffffu, den[h], o);
        inv[h] = 1.f / fmaxf(den[h], 1e-16f);
    }
    float acc[R];
    #pragma unroll
    for (int j = 0; j < R; j++) acc[j] = 0.f;
    for (int j0 = 0; j0 < cnt; j0 += 32) {
        int jj = j0 + lane;
        if (jj < cnt) {
            ssm2[warp][lane] = psrc[r0 + jj];
            #pragma unroll
            for (int h = 0; h < H; h++)
                csm[warp][lane * H + h] = expf(slog[(size_t)(r0 + jj) * H + h] - mx[h]) * inv[h];
        }
        __syncwarp();
        int lim = min(32, cnt - j0);
        for (int k = 0; k < lim; k++) {
            int s = ssm2[warp][k];
            const float* row = xl + (size_t)s * STRIDE;
            if (H == 2) {
                float c0 = csm[warp][k * 2], c1 = csm[warp][k * 2 + 1];
                #pragma unroll
                for (int j = 0; j < R; j++)
                    acc[j] = fmaf((j < R / 2) ? c0 : c1, row[j * 32 + lane], acc[j]);
            } else {
                float c0 = csm[warp][k];
                #pragma unroll
                for (int j = 0; j < R; j++)
                    acc[j] = fmaf(c0, row[j * 32 + lane], acc[j]);
            }
        }
        __syncwarp();
    }
    float v[4];
    #pragma unroll
    for (int j = 0; j < 4; j++) {
        if (H == 2) v[j] = 0.5f * (acc[j] + acc[j + 4]) + bias[j * 32 + lane];
        else        v[j] = acc[j] + bias[j * 32 + lane];
    }
    float s = v[0] + v[1] + v[2] + v[3];
    #pragma unroll
    for (int o = 16; o; o >>= 1) s += __shfl_xor_sync(0xffffffffu, s, o);
    float mu = s * (1.f / 128.f);
    float sq = 0.f;
    #pragma unroll
    for (int j = 0; j < 4; j++) { v[j] -= mu; sq = fmaf(v[j], v[j], sq); }
    #pragma unroll
    for (int o = 16; o; o >>= 1) sq += __shfl_xor_sync(0xffffffffu, sq, o);
    float is = rsqrtf(sq * (1.f / 128.f) + 1e-5f);
    #pragma unroll
    for (int j = 0; j < 4; j++) {
        int oi = j * 32 + lane;
        float o2 = v[j] * is * gg[oi] + bb[oi];
        out[(size_t)node * 128 + oi] = o2 > 0.f ? o2 : (expf(o2) - 1.f);
    }
}

// ---------------- classifier edge pass ----------------
__global__ void __launch_bounds__(256)
k_cls_edge(const float* __restrict__ pre12, const float* __restrict__ pre3,
           const int* __restrict__ src, const int* __restrict__ dst,
           const float* __restrict__ c1b, const float* __restrict__ c2w,
           const float* __restrict__ c2b, const float* __restrict__ c3w,
           const float* __restrict__ c3b, float* __restrict__ out) {
    __shared__ float c2s[HID * 64];
    __shared__ float hb[8][HID];
    __shared__ float b1s[HID];
    __shared__ float b2s[64];
    __shared__ float c3s[64];
    int tid = threadIdx.x;
    for (int i = tid; i < HID * 64; i += 256) c2s[i] = c2w[i];
    if (tid < HID) b1s[tid] = c1b[tid];
    if (tid < 64)  { b2s[tid] = c2b[tid]; c3s[tid] = c3w[tid]; }
    __syncthreads();
    const ull* c2p = (const ull*)c2s;
    float c3bv = c3b[0];
    int warp = tid >> 5, lane = tid & 31;
    float* h1r = hb[warp];
    const int stride = gridDim.x * 8;
    for (int e = blockIdx.x * 8 + warp; e < EE; e += stride) {
        int s = src[e], d = dst[e];
        float4 p1 = *(const float4*)(pre12 + (size_t)s * 256 + lane * 4);
        float4 p2 = *(const float4*)(pre12 + (size_t)d * 256 + 128 + lane * 4);
        float4 p3 = *(const float4*)(pre3 + (size_t)e * HID + lane * 4);
        float4 bb = ((const float4*)b1s)[lane];
        float4 h;
        h.x = fmaxf(p1.x + p2.x + p3.x + bb.x, 0.f);
        h.y = fmaxf(p1.y + p2.y + p3.y + bb.y, 0.f);
        h.z = fmaxf(p1.z + p2.z + p3.z + bb.z, 0.f);
        h.w = fmaxf(p1.w + p2.w + p3.w + bb.w, 0.f);
        __syncwarp();
        ((float4*)h1r)[lane] = h;
        __syncwarp();
        ull acc = pk2(b2s[lane * 2], b2s[lane * 2 + 1]);
        #pragma unroll 8
        for (int k = 0; k < HID; k++)
            acc = ffma2(dup2(h1r[k]), c2p[k * 32 + lane], acc);
        float x, y; upk2(acc, x, y);
        float v = fmaxf(x, 0.f) * c3s[lane * 2] + fmaxf(y, 0.f) * c3s[lane * 2 + 1];
        #pragma unroll
        for (int o = 16; o; o >>= 1) v += __shfl_xor_sync(0xffffffffu, v, o);
        if (lane == 0) out[e] = v + c3bv;
    }
}

// ---------------- launch ----------------
static inline int cdiv(long a, long b) { return (int)((a + b - 1) / b); }

extern "C" void kernel_launch(void* const* d_in, const int* in_sizes, int n_in,
                              void* d_out, int out_size) {
    const float* node_stats = (const float*)d_in[1];
    const int*   ei   = (const int*)d_in[2];
    const int*   src  = ei;
    const int*   dst  = ei + EE;
    const float* ea   = (const float*)d_in[3];
    const float* epw  = (const float*)d_in[4];
    const float* epb  = (const float*)d_in[5];
    const float* g1wl = (const float*)d_in[6];
    const float* g1wr = (const float*)d_in[7];
    const float* g1we = (const float*)d_in[8];
    const float* g1att= (const float*)d_in[9];
    const float* g1b  = (const float*)d_in[10];
    const float* n1g  = (const float*)d_in[11];
    const float* n1b  = (const float*)d_in[12];
    const float* g2wl = (const float*)d_in[13];
    const float* g2wr = (const float*)d_in[14];
    const float* g2we = (const float*)d_in[15];
    const float* g2att= (const float*)d_in[16];
    const float* g2b  = (const float*)d_in[17];
    const float* n2g  = (const float*)d_in[18];
    const float* n2b  = (const float*)d_in[19];
    const float* c1w  = (const float*)d_in[20];
    const float* c1b  = (const float*)d_in[21];
    const float* c2w  = (const float*)d_in[22];
    const float* c2b  = (const float*)d_in[23];
    const float* c3w  = (const float*)d_in[24];
    const float* c3b  = (const float*)d_in[25];
    float* out = (float*)d_out;

    float *xsum_out, *xsum_in, *loop, *xi, *xlr1, *xlr2, *pre12, *wpack;
    float *logit1, *h1, *logit2, *h2, *ew;
    int *deg_out, *deg_in, *rowptr, *cursor, *psrc, *ipos;
    cudaGetSymbolAddress((void**)&xsum_out, g_xsum_out);
    cudaGetSymbolAddress((void**)&xsum_in,  g_xsum_in);
    cudaGetSymbolAddress((void**)&deg_out,  g_deg_out);
    cudaGetSymbolAddress((void**)&deg_in,   g_deg_in);
    cudaGetSymbolAddress((void**)&loop,     g_loop);
    cudaGetSymbolAddress((void**)&xi,       g_xi);
    cudaGetSymbolAddress((void**)&xlr1,     g_xlr1);
    cudaGetSymbolAddress((void**)&xlr2,     g_xlr2);
    cudaGetSymbolAddress((void**)&pre12,    g_pre12);
    cudaGetSymbolAddress((void**)&wpack,    g_wpack);
    cudaGetSymbolAddress((void**)&logit1,   g_logit1);
    cudaGetSymbolAddress((void**)&h1,       g_h1);
    cudaGetSymbolAddress((void**)&logit2,   g_logit2);
    cudaGetSymbolAddress((void**)&h2,       g_h2);
    cudaGetSymbolAddress((void**)&rowptr,   g_rowptr);
    cudaGetSymbolAddress((void**)&cursor,   g_cursor);
    cudaGetSymbolAddress((void**)&psrc,     g_psrc);
    cudaGetSymbolAddress((void**)&ipos,     g_ipos);
    cudaGetSymbolAddress((void**)&ew,       g_ew);

    cudaMemsetAsync(xsum_out, 0, sizeof(float) * NN * ND);
    cudaMemsetAsync(xsum_in,  0, sizeof(float) * NN * ND);
    cudaMemsetAsync(deg_out,  0, sizeof(int) * NN);
    cudaMemsetAsync(deg_in,   0, sizeof(int) * NN);
    cudaMemsetAsync(loop,     0, sizeof(float) * NN * ED);

    // slot 1..3
    k_embed_scatter<<<2048, 256>>>(src, dst, ea, epw, epb, xsum_out, xsum_in,
                                   deg_out, deg_in, loop);
    k_build_xi<<<cdiv((long)NN * GIN, 256), 256>>>(node_stats, xsum_out, xsum_in, deg_out, deg_in, xi);
    k_loop_div<<<cdiv((long)NN * ED, 256), 256>>>(loop, deg_in);
    // slot 4 = PROFILED: ew1 GEMM [400k,64]@[64,256] with new 128x128 tile
    k_gemm<<<dim3(2, cdiv(EE, BM)), 256>>>(ea, g1we, ew, EE, ED, 256);
    k_gemm<<<dim3(2, cdiv(NN, BM)), 256>>>(loop, g1we, ew + (size_t)EE * 256, NN, ED, 256);

    k_prefix<<<1, 1024>>>(deg_in, rowptr, cursor);
    k_perm<<<cdiv(E2T, 256), 256>>>(src, dst, cursor, psrc, ipos);

    // GAT layer 1: merged xl|xr GEMM
    k_pack2<<<cdiv((long)GIN * 512, 256), 256>>>(g1wl, g1wr, wpack, GIN, 256, 256);
    k_gemm<<<dim3(4, cdiv(NN, BM)), 256>>>(xi, wpack, xlr1, NN, GIN, 512);
    k_logit_add<256, 2, 512><<<cdiv((long)E2T * 32, 256), 256>>>(xlr1, ew, g1att, src, dst, ipos, logit1);
    k_gat_reduce<256, 2, 512><<<cdiv(NN, 8), 256>>>(xlr1, logit1, rowptr, psrc, g1b, n1g, n1b, h1);

    // GAT layer 2
    k_gemm<<<dim3(1, cdiv(EE, BM)), 256>>>(ea, g2we, ew, EE, ED, HID);
    k_gemm<<<dim3(1, cdiv(NN, BM)), 256>>>(loop, g2we, ew + (size_t)EE * HID, NN, ED, HID);
    k_pack2<<<cdiv((long)HID * 256, 256), 256>>>(g2wl, g2wr, wpack, HID, HID, HID);
    k_gemm<<<dim3(2, cdiv(NN, BM)), 256>>>(h1, wpack, xlr2, NN, HID, 256);
    k_logit_add<128, 1, 256><<<cdiv((long)E2T * 32, 256), 256>>>(xlr2, ew, g2att, src, dst, ipos, logit2);
    k_gat_reduce<128, 1, 256><<<cdiv(NN, 8), 256>>>(xlr2, logit2, rowptr, psrc, g2b, n2g, n2b, h2);

    // classifier: merged pre1|pre2 GEMM + pre3 GEMM + edge pass
    k_pack2<<<cdiv((long)HID * 256, 256), 256>>>(c1w, c1w + 128 * HID, wpack, HID, HID, HID);
    k_gemm<<<dim3(2, cdiv(NN, BM)), 256>>>(h2, wpack, pre12, NN, HID, 256);
    k_gemm<<<dim3(1, cdiv(EE, BM)), 256>>>(ea, c1w + 256 * HID, ew, EE, ED, HID);
    k_cls_edge<<<592, 256>>>(pre12, ew, src, dst, c1b, c2w, c2b, c3w, c3b, out);
}

// round 13
// speedup vs baseline: 1.2330x; 1.2330x over previous
#include <cuda_runtime.h>
#include <math.h>
#include <float.h>

#define NN 50000
#define EE 400000
#define E2T (EE + NN)
#define ND 128
#define ED 64
#define HID 128
#define GIN 258
#define CIN 320

typedef unsigned long long ull;

// ---------------- packed f32x2 helpers ----------------
__device__ __forceinline__ ull pk2(float lo, float hi) {
    ull r; asm("mov.b64 %0,{%1,%2};" : "=l"(r) : "f"(lo), "f"(hi)); return r;
}
__device__ __forceinline__ ull dup2(float v) { return pk2(v, v); }
__device__ __forceinline__ void upk2(ull p, float& lo, float& hi) {
    asm("mov.b64 {%0,%1},%2;" : "=f"(lo), "=f"(hi) : "l"(p));
}
__device__ __forceinline__ ull ffma2(ull a, ull b, ull c) {
    ull d; asm("fma.rn.f32x2 %0,%1,%2,%3;" : "=l"(d) : "l"(a), "l"(b), "l"(c)); return d;
}

// ---------------- scratch ----------------
__device__ float g_xsum_out[NN * ND];
__device__ float g_xsum_in [NN * ND];
__device__ int   g_deg_out [NN];
__device__ int   g_deg_in  [NN];
__device__ float g_loop    [NN * ED];
__device__ float g_xi      [NN * GIN];
__device__ float g_xlr1    [(size_t)NN * 512];
__device__ float g_xlr2    [NN * 256];
__device__ float g_pre12   [NN * 256];
__device__ float g_wpack   [258 * 512];
__device__ float g_logit1  [E2T * 2];
__device__ float g_h1      [NN * HID];
__device__ float g_logit2  [E2T];
__device__ float g_h2      [NN * HID];
__device__ int   g_rowptr  [NN + 1];
__device__ int   g_cursor  [NN];
__device__ int   g_psrc    [E2T];
__device__ int   g_ipos    [E2T];
__device__ float g_ew      [(size_t)E2T * 256];

// ---------------- stage 1+2 fused: embed + scatter + degrees + loop sums -------------
__global__ void k_embed_scatter(const int* __restrict__ src, const int* __restrict__ dst,
                                const float* __restrict__ ea,
                                const float* __restrict__ epw, const float* __restrict__ epb,
                                float* __restrict__ xsum_out, float* __restrict__ xsum_in,
                                int* __restrict__ deg_out, int* __restrict__ deg_in,
                                float* __restrict__ loop) {
    __shared__ float4 wsh[ED * 32];
    __shared__ float4 bsh4[32];
    __shared__ float  easm[16][ED];
    int tid = threadIdx.x;
    for (int i = tid; i < ED * 32; i += 256) wsh[i] = ((const float4*)epw)[i];
    if (tid < 32) bsh4[tid] = ((const float4*)epb)[tid];
    __syncthreads();
    const ulonglong2* wsh2 = (const ulonglong2*)wsh;
    int sub = tid >> 5;
    int q   = tid & 31;
    for (int base = blockIdx.x * 16; base < EE; base += gridDim.x * 16) {
        #pragma unroll
        for (int r = 0; r < 4; r++) {
            int idx = tid + r * 256;
            int ee = base + (idx >> 6);
            if (ee < EE) easm[idx >> 6][idx & 63] = ea[(size_t)ee * ED + (idx & 63)];
        }
        __syncthreads();
        {
            int e_loc = tid >> 4, q2 = tid & 15;
            int e = base + e_loc;
            if (e < EE) {
                int d = dst[e];
                if (q2 == 0) {
                    atomicAdd(&deg_in[d], 1);
                    atomicAdd(&deg_out[src[e]], 1);
                }
                float4 v = ((const float4*)easm[e_loc])[q2];
                atomicAdd((float4*)(loop + (size_t)d * ED + q2 * 4), v);
            }
        }
        int e0 = base + sub, e1 = base + sub + 8;
        float4 bb = bsh4[q];
        ull a0[2] = { pk2(bb.x, bb.y), pk2(bb.z, bb.w) };
        ull a1[2] = { a0[0], a0[1] };
        const float* er0 = easm[sub];
        const float* er1 = easm[sub + 8];
        #pragma unroll
        for (int k = 0; k < ED; k++) {
            ulonglong2 w2 = wsh2[k * 32 + q];
            ull b0 = dup2(er0[k]), b1 = dup2(er1[k]);
            a0[0] = ffma2(b0, w2.x, a0[0]); a0[1] = ffma2(b0, w2.y, a0[1]);
            a1[0] = ffma2(b1, w2.x, a1[0]); a1[1] = ffma2(b1, w2.y, a1[1]);
        }
        if (e0 < EE) {
            float4 o; upk2(a0[0], o.x, o.y); upk2(a0[1], o.z, o.w);
            o.x = fmaxf(o.x, 0.f); o.y = fmaxf(o.y, 0.f); o.z = fmaxf(o.z, 0.f); o.w = fmaxf(o.w, 0.f);
            int s = src[e0], d = dst[e0];
            atomicAdd((float4*)(xsum_out + (size_t)s * ND + q * 4), o);
            atomicAdd((float4*)(xsum_in  + (size_t)d * ND + q * 4), o);
        }
        if (e1 < EE) {
            float4 o; upk2(a1[0], o.x, o.y); upk2(a1[1], o.z, o.w);
            o.x = fmaxf(o.x, 0.f); o.y = fmaxf(o.y, 0.f); o.z = fmaxf(o.z, 0.f); o.w = fmaxf(o.w, 0.f);
            int s = src[e1], d = dst[e1];
            atomicAdd((float4*)(xsum_out + (size_t)s * ND + q * 4), o);
            atomicAdd((float4*)(xsum_in  + (size_t)d * ND + q * 4), o);
        }
        __syncthreads();
    }
}

// ---------------- stage 3: build xi, finalize loop_attr ----------------
__global__ void k_build_xi(const float* __restrict__ node_stats,
                           const float* __restrict__ xsum_out, const float* __restrict__ xsum_in,
                           const int* __restrict__ deg_out, const int* __restrict__ deg_in,
                           float* __restrict__ xi) {
    int tid = blockIdx.x * blockDim.x + threadIdx.x;
    if (tid >= NN * GIN) return;
    int i = tid / GIN, j = tid - i * GIN;
    float v;
    if (j < 128)      v = xsum_out[i * 128 + j]        / fmaxf((float)deg_out[i], 1.f);
    else if (j < 256) v = xsum_in [i * 128 + (j - 128)] / fmaxf((float)deg_in [i], 1.f);
    else              v = node_stats[i * 2 + (j - 256)];
    xi[tid] = v;
}

__global__ void k_loop_div(float* __restrict__ loop, const int* __restrict__ deg_in) {
    int tid = blockIdx.x * blockDim.x + threadIdx.x;
    if (tid >= NN * ED) return;
    int i = tid >> 6;
    loop[tid] = loop[tid] / fmaxf((float)deg_in[i], 1.f);
}

// ---------------- CSR prefix scan ----------------
__global__ void k_prefix(const int* __restrict__ deg_in, int* __restrict__ rowptr,
                         int* __restrict__ cursor) {
    __shared__ int wsums[32];
    __shared__ int carry_s;
    int t = threadIdx.x, lane = t & 31, wid = t >> 5;
    if (t == 0) carry_s = 0;
    __syncthreads();
    for (int base = 0; base < NN; base += 1024) {
        int n = base + t;
        int v = (n < NN) ? deg_in[n] + 1 : 0;
        int x = v;
        #pragma unroll
        for (int o = 1; o < 32; o <<= 1) {
            int y = __shfl_up_sync(0xffffffffu, x, o);
            if (lane >= o) x += y;
        }
        if (lane == 31) wsums[wid] = x;
        __syncthreads();
        if (wid == 0) {
            int s = wsums[lane];
            #pragma unroll
            for (int o = 1; o < 32; o <<= 1) {
                int y = __shfl_up_sync(0xffffffffu, s, o);
                if (lane >= o) s += y;
            }
            wsums[lane] = s;
        }
        __syncthreads();
        int excl = x - v + (wid > 0 ? wsums[wid - 1] : 0) + carry_s;
        if (n < NN) { rowptr[n] = excl; cursor[n] = excl; }
        __syncthreads();
        if (t == 0) carry_s += wsums[31];
        __syncthreads();
    }
    if (t == 0) rowptr[NN] = E2T;
}

__global__ void k_perm(const int* __restrict__ src, const int* __restrict__ dst,
                       int* __restrict__ cursor, int* __restrict__ psrc,
                       int* __restrict__ ipos) {
    int e = blockIdx.x * blockDim.x + threadIdx.x;
    if (e < EE) {
        int pos = atomicAdd(&cursor[dst[e]], 1);
        psrc[pos] = src[e];
        ipos[e] = pos;
    } else if (e < E2T) {
        int i = e - EE;
        int pos = atomicAdd(&cursor[i], 1);
        psrc[pos] = i;
        ipos[e] = pos;
    }
}

// ---------------- weight pack ----------------
__global__ void k_pack2(const float* __restrict__ B1, const float* __restrict__ B2,
                        float* __restrict__ C, int K, int N1, int N2) {
    int i = blockIdx.x * 256 + threadIdx.x;
    int N = N1 + N2;
    if (i >= K * N) return;
    int k = i / N, c = i - k * N;
    C[i] = (c < N1) ? B1[k * N1 + c] : B2[k * N2 + (c - N1)];
}

// ---------------- fp32 tiled GEMM with FFMA2: 128x64 tile, 8x4/thread (R11 version) --
#define BM 128
#define BN 64
#define BKK 16
__global__ void __launch_bounds__(256, 3)
k_gemm(const float* __restrict__ A, const float* __restrict__ B,
       float* __restrict__ C, int M, int K, int Nc) {
    __shared__ float As[BKK][BM + 4];
    __shared__ float Bs[BKK][BN + 4];
    int brow = blockIdx.y * BM, bcol = blockIdx.x * BN;
    int tid = threadIdx.x;
    int tr = tid >> 4, tc = tid & 15;
    ull acc[8][2];
    #pragma unroll
    for (int i = 0; i < 8; i++) { acc[i][0] = 0ull; acc[i][1] = 0ull; }
    for (int k0 = 0; k0 < K; k0 += BKK) {
        #pragma unroll
        for (int it = 0; it < 4; it++) {
            int idx = tid + it * 256;
            int r = idx >> 3, c2 = idx & 7;
            int gr = brow + r, gc = k0 + c2 * 2;
            float2 v = make_float2(0.f, 0.f);
            if (gr < M) {
                if (gc + 1 < K)  v = *(const float2*)&A[(size_t)gr * K + gc];
                else if (gc < K) v.x = A[(size_t)gr * K + gc];
            }
            As[c2 * 2][r] = v.x;
            As[c2 * 2 + 1][r] = v.y;
        }
        {
            int r = tid >> 4, c4 = tid & 15;
            int gr = k0 + r;
            float4 v = make_float4(0.f, 0.f, 0.f, 0.f);
            if (gr < K) v = *(const float4*)&B[(size_t)gr * Nc + bcol + c4 * 4];
            *(float4*)&Bs[r][c4 * 4] = v;
        }
        __syncthreads();
        #pragma unroll
        for (int kk = 0; kk < BKK; kk++) {
            float4 a0 = *(const float4*)&As[kk][tr * 8];
            float4 a1 = *(const float4*)&As[kk][tr * 8 + 4];
            ulonglong2 b2 = *(const ulonglong2*)&Bs[kk][tc * 4];
            ull d;
            d = dup2(a0.x); acc[0][0] = ffma2(d, b2.x, acc[0][0]); acc[0][1] = ffma2(d, b2.y, acc[0][1]);
            d = dup2(a0.y); acc[1][0] = ffma2(d, b2.x, acc[1][0]); acc[1][1] = ffma2(d, b2.y, acc[1][1]);
            d = dup2(a0.z); acc[2][0] = ffma2(d, b2.x, acc[2][0]); acc[2][1] = ffma2(d, b2.y, acc[2][1]);
            d = dup2(a0.w); acc[3][0] = ffma2(d, b2.x, acc[3][0]); acc[3][1] = ffma2(d, b2.y, acc[3][1]);
            d = dup2(a1.x); acc[4][0] = ffma2(d, b2.x, acc[4][0]); acc[4][1] = ffma2(d, b2.y, acc[4][1]);
            d = dup2(a1.y); acc[5][0] = ffma2(d, b2.x, acc[5][0]); acc[5][1] = ffma2(d, b2.y, acc[5][1]);
            d = dup2(a1.z); acc[6][0] = ffma2(d, b2.x, acc[6][0]); acc[6][1] = ffma2(d, b2.y, acc[6][1]);
            d = dup2(a1.w); acc[7][0] = ffma2(d, b2.x, acc[7][0]); acc[7][1] = ffma2(d, b2.y, acc[7][1]);
        }
        __syncthreads();
    }
    #pragma unroll
    for (int i = 0; i < 8; i++) {
        int row = brow + tr * 8 + i;
        if (row >= M) continue;
        float v[4];
        upk2(acc[i][0], v[0], v[1]); upk2(acc[i][1], v[2], v[3]);
        #pragma unroll
        for (int j = 0; j < 4; j++) {
            int col = bcol + tc * 4 + j;
            if (col < Nc) C[(size_t)row * Nc + col] = v[j];
        }
    }
}

// ---------------- logits add pass: warp per edge; xl/xr packed in one buffer ----------
template <int OUT, int H, int STRIDE>
__global__ void __launch_bounds__(256)
k_logit_add(const float* __restrict__ xlr, const float* __restrict__ ew,
            const float* __restrict__ att,
            const int* __restrict__ src, const int* __restrict__ dst,
            const int* __restrict__ ipos, float* __restrict__ logit) {
    int gw = (blockIdx.x * 256 + threadIdx.x) >> 5;
    int lane = threadIdx.x & 31;
    if (gw >= E2T) return;
    int e = gw;
    int s, d;
    if (e < EE) { s = src[e]; d = dst[e]; } else { s = d = e - EE; }
    const float* xls = xlr + (size_t)s * STRIDE;
    const float* xrd = xlr + (size_t)d * STRIDE + OUT;
    const float* ewe = ew + (size_t)e * OUT;
    float4 a0 = *(const float4*)(xls + lane * 4);
    float4 b0 = *(const float4*)(xrd + lane * 4);
    float4 c0 = *(const float4*)(ewe + lane * 4);
    float4 t0 = *(const float4*)(att + lane * 4);
    float v0, p0 = 0.f;
    v0 = a0.x + b0.x + c0.x; v0 = v0 > 0.f ? v0 : 0.2f * v0; p0 = fmaf(v0, t0.x, p0);
    v0 = a0.y + b0.y + c0.y; v0 = v0 > 0.f ? v0 : 0.2f * v0; p0 = fmaf(v0, t0.y, p0);
    v0 = a0.z + b0.z + c0.z; v0 = v0 > 0.f ? v0 : 0.2f * v0; p0 = fmaf(v0, t0.z, p0);
    v0 = a0.w + b0.w + c0.w; v0 = v0 > 0.f ? v0 : 0.2f * v0; p0 = fmaf(v0, t0.w, p0);
    float p1 = 0.f;
    if (H == 2) {
        float4 a1 = *(const float4*)(xls + 128 + lane * 4);
        float4 b1 = *(const float4*)(xrd + 128 + lane * 4);
        float4 c1 = *(const float4*)(ewe + 128 + lane * 4);
        float4 t1 = *(const float4*)(att + 128 + lane * 4);
        float v1;
        v1 = a1.x + b1.x + c1.x; v1 = v1 > 0.f ? v1 : 0.2f * v1; p1 = fmaf(v1, t1.x, p1);
        v1 = a1.y + b1.y + c1.y; v1 = v1 > 0.f ? v1 : 0.2f * v1; p1 = fmaf(v1, t1.y, p1);
        v1 = a1.z + b1.z + c1.z; v1 = v1 > 0.f ? v1 : 0.2f * v1; p1 = fmaf(v1, t1.z, p1);
        v1 = a1.w + b1.w + c1.w; v1 = v1 > 0.f ? v1 : 0.2f * v1; p1 = fmaf(v1, t1.w, p1);
    }
    #pragma unroll
    for (int o = 16; o; o >>= 1) {
        p0 += __shfl_xor_sync(0xffffffffu, p0, o);
        if (H == 2) p1 += __shfl_xor_sync(0xffffffffu, p1, o);
    }
    if (lane == 0) {
        int pos = ipos[e];
        if (H == 2) { logit[(size_t)pos * 2] = p0; logit[(size_t)pos * 2 + 1] = p1; }
        else        logit[pos] = p0;
    }
}

// ---------------- GATv2 fused reduce ----------------
template <int OUT, int H, int STRIDE>
__global__ void __launch_bounds__(256)
k_gat_reduce(const float* __restrict__ xl, const float* __restrict__ slog,
             const int* __restrict__ rowptr, const int* __restrict__ psrc,
             const float* __restrict__ bias, const float* __restrict__ gg,
             const float* __restrict__ bb, float* __restrict__ out) {
    const int R = OUT / 32;
    __shared__ float csm[8][32 * H];
    __shared__ int   ssm2[8][32];
    int warp = threadIdx.x >> 5, lane = threadIdx.x & 31;
    int node = blockIdx.x * 8 + warp;
    if (node >= NN) return;
    int r0 = rowptr[node], r1 = rowptr[node + 1], cnt = r1 - r0;
    float mx[H];
    #pragma unroll
    for (int h = 0; h < H; h++) mx[h] = -FLT_MAX;
    for (int j = lane; j < cnt; j += 32) {
        #pragma unroll
        for (int h = 0; h < H; h++) mx[h] = fmaxf(mx[h], slog[(size_t)(r0 + j) * H + h]);
    }
    #pragma unroll
    for (int h = 0; h < H; h++)
        #pragma unroll
        for (int o = 16; o; o >>= 1) mx[h] = fmaxf(mx[h], __shfl_xor_sync(0xffffffffu, mx[h], o));
    float den[H];
    #pragma unroll
    for (int h = 0; h < H; h++) den[h] = 0.f;
    for (int j = lane; j < cnt; j += 32) {
        #pragma unroll
        for (int h = 0; h < H; h++) den[h] += expf(slog[(size_t)(r0 + j) * H + h] - mx[h]);
    }
    float inv[H];
    #pragma unroll
    for (int h = 0; h < H; h++) {
        #pragma unroll
        for (int o = 16; o; o >>= 1) den[h] += __shfl_xor_sync(0xffffffffu, den[h], o);
        inv[h] = 1.f / fmaxf(den[h], 1e-16f);
    }
    float acc[R];
    #pragma unroll
    for (int j = 0; j < R; j++) acc[j] = 0.f;
    for (int j0 = 0; j0 < cnt; j0 += 32) {
        int jj = j0 + lane;
        if (jj < cnt) {
            ssm2[warp][lane] = psrc[r0 + jj];
            #pragma unroll
            for (int h = 0; h < H; h++)
                csm[warp][lane * H + h] = expf(slog[(size_t)(r0 + jj) * H + h] - mx[h]) * inv[h];
        }
        __syncwarp();
        int lim = min(32, cnt - j0);
        for (int k = 0; k < lim; k++) {
            int s = ssm2[warp][k];
            const float* row = xl + (size_t)s * STRIDE;
            if (H == 2) {
                float c0 = csm[warp][k * 2], c1 = csm[warp][k * 2 + 1];
                #pragma unroll
                for (int j = 0; j < R; j++)
                    acc[j] = fmaf((j < R / 2) ? c0 : c1, row[j * 32 + lane], acc[j]);
            } else {
                float c0 = csm[warp][k];
                #pragma unroll
                for (int j = 0; j < R; j++)
                    acc[j] = fmaf(c0, row[j * 32 + lane], acc[j]);
            }
        }
        __syncwarp();
    }
    float v[4];
    #pragma unroll
    for (int j = 0; j < 4; j++) {
        if (H == 2) v[j] = 0.5f * (acc[j] + acc[j + 4]) + bias[j * 32 + lane];
        else        v[j] = acc[j] + bias[j * 32 + lane];
    }
    float s = v[0] + v[1] + v[2] + v[3];
    #pragma unroll
    for (int o = 16; o; o >>= 1) s += __shfl_xor_sync(0xffffffffu, s, o);
    float mu = s * (1.f / 128.f);
    float sq = 0.f;
    #pragma unroll
    for (int j = 0; j < 4; j++) { v[j] -= mu; sq = fmaf(v[j], v[j], sq); }
    #pragma unroll
    for (int o = 16; o; o >>= 1) sq += __shfl_xor_sync(0xffffffffu, sq, o);
    float is = rsqrtf(sq * (1.f / 128.f) + 1e-5f);
    #pragma unroll
    for (int j = 0; j < 4; j++) {
        int oi = j * 32 + lane;
        float o2 = v[j] * is * gg[oi] + bb[oi];
        out[(size_t)node * 128 + oi] = o2 > 0.f ? o2 : (expf(o2) - 1.f);
    }
}

// ---------------- classifier edge pass ----------------
__global__ void __launch_bounds__(256)
k_cls_edge(const float* __restrict__ pre12, const float* __restrict__ pre3,
           const int* __restrict__ src, const int* __restrict__ dst,
           const float* __restrict__ c1b, const float* __restrict__ c2w,
           const float* __restrict__ c2b, const float* __restrict__ c3w,
           const float* __restrict__ c3b, float* __restrict__ out) {
    __shared__ float c2s[HID * 64];
    __shared__ float hb[8][HID];
    __shared__ float b1s[HID];
    __shared__ float b2s[64];
    __shared__ float c3s[64];
    int tid = threadIdx.x;
    for (int i = tid; i < HID * 64; i += 256) c2s[i] = c2w[i];
    if (tid < HID) b1s[tid] = c1b[tid];
    if (tid < 64)  { b2s[tid] = c2b[tid]; c3s[tid] = c3w[tid]; }
    __syncthreads();
    const ull* c2p = (const ull*)c2s;
    float c3bv = c3b[0];
    int warp = tid >> 5, lane = tid & 31;
    float* h1r = hb[warp];
    const int stride = gridDim.x * 8;
    for (int e = blockIdx.x * 8 + warp; e < EE; e += stride) {
        int s = src[e], d = dst[e];
        float4 p1 = *(const float4*)(pre12 + (size_t)s * 256 + lane * 4);
        float4 p2 = *(const float4*)(pre12 + (size_t)d * 256 + 128 + lane * 4);
        float4 p3 = *(const float4*)(pre3 + (size_t)e * HID + lane * 4);
        float4 bb = ((const float4*)b1s)[lane];
        float4 h;
        h.x = fmaxf(p1.x + p2.x + p3.x + bb.x, 0.f);
        h.y = fmaxf(p1.y + p2.y + p3.y + bb.y, 0.f);
        h.z = fmaxf(p1.z + p2.z + p3.z + bb.z, 0.f);
        h.w = fmaxf(p1.w + p2.w + p3.w + bb.w, 0.f);
        __syncwarp();
        ((float4*)h1r)[lane] = h;
        __syncwarp();
        ull acc = pk2(b2s[lane * 2], b2s[lane * 2 + 1]);
        #pragma unroll 8
        for (int k = 0; k < HID; k++)
            acc = ffma2(dup2(h1r[k]), c2p[k * 32 + lane], acc);
        float x, y; upk2(acc, x, y);
        float v = fmaxf(x, 0.f) * c3s[lane * 2] + fmaxf(y, 0.f) * c3s[lane * 2 + 1];
        #pragma unroll
        for (int o = 16; o; o >>= 1) v += __shfl_xor_sync(0xffffffffu, v, o);
        if (lane == 0) out[e] = v + c3bv;
    }
}

// ---------------- launch ----------------
static inline int cdiv(long a, long b) { return (int)((a + b - 1) / b); }

extern "C" void kernel_launch(void* const* d_in, const int* in_sizes, int n_in,
                              void* d_out, int out_size) {
    const float* node_stats = (const float*)d_in[1];
    const int*   ei   = (const int*)d_in[2];
    const int*   src  = ei;
    const int*   dst  = ei + EE;
    const float* ea   = (const float*)d_in[3];
    const float* epw  = (const float*)d_in[4];
    const float* epb  = (const float*)d_in[5];
    const float* g1wl = (const float*)d_in[6];
    const float* g1wr = (const float*)d_in[7];
    const float* g1we = (const float*)d_in[8];
    const float* g1att= (const float*)d_in[9];
    const float* g1b  = (const float*)d_in[10];
    const float* n1g  = (const float*)d_in[11];
    const float* n1b  = (const float*)d_in[12];
    const float* g2wl = (const float*)d_in[13];
    const float* g2wr = (const float*)d_in[14];
    const float* g2we = (const float*)d_in[15];
    const float* g2att= (const float*)d_in[16];
    const float* g2b  = (const float*)d_in[17];
    const float* n2g  = (const float*)d_in[18];
    const float* n2b  = (const float*)d_in[19];
    const float* c1w  = (const float*)d_in[20];
    const float* c1b  = (const float*)d_in[21];
    const float* c2w  = (const float*)d_in[22];
    const float* c2b  = (const float*)d_in[23];
    const float* c3w  = (const float*)d_in[24];
    const float* c3b  = (const float*)d_in[25];
    float* out = (float*)d_out;

    float *xsum_out, *xsum_in, *loop, *xi, *xlr1, *xlr2, *pre12, *wpack;
    float *logit1, *h1, *logit2, *h2, *ew;
    int *deg_out, *deg_in, *rowptr, *cursor, *psrc, *ipos;
    cudaGetSymbolAddress((void**)&xsum_out, g_xsum_out);
    cudaGetSymbolAddress((void**)&xsum_in,  g_xsum_in);
    cudaGetSymbolAddress((void**)&deg_out,  g_deg_out);
    cudaGetSymbolAddress((void**)&deg_in,   g_deg_in);
    cudaGetSymbolAddress((void**)&loop,     g_loop);
    cudaGetSymbolAddress((void**)&xi,       g_xi);
    cudaGetSymbolAddress((void**)&xlr1,     g_xlr1);
    cudaGetSymbolAddress((void**)&xlr2,     g_xlr2);
    cudaGetSymbolAddress((void**)&pre12,    g_pre12);
    cudaGetSymbolAddress((void**)&wpack,    g_wpack);
    cudaGetSymbolAddress((void**)&logit1,   g_logit1);
    cudaGetSymbolAddress((void**)&h1,       g_h1);
    cudaGetSymbolAddress((void**)&logit2,   g_logit2);
    cudaGetSymbolAddress((void**)&h2,       g_h2);
    cudaGetSymbolAddress((void**)&rowptr,   g_rowptr);
    cudaGetSymbolAddress((void**)&cursor,   g_cursor);
    cudaGetSymbolAddress((void**)&psrc,     g_psrc);
    cudaGetSymbolAddress((void**)&ipos,     g_ipos);
    cudaGetSymbolAddress((void**)&ew,       g_ew);

    cudaMemsetAsync(xsum_out, 0, sizeof(float) * NN * ND);
    cudaMemsetAsync(xsum_in,  0, sizeof(float) * NN * ND);
    cudaMemsetAsync(deg_out,  0, sizeof(int) * NN);
    cudaMemsetAsync(deg_in,   0, sizeof(int) * NN);
    cudaMemsetAsync(loop,     0, sizeof(float) * NN * ED);

    // slot 1..3
    k_embed_scatter<<<2048, 256>>>(src, dst, ea, epw, epb, xsum_out, xsum_in,
                                   deg_out, deg_in, loop);
    k_build_xi<<<cdiv((long)NN * GIN, 256), 256>>>(node_stats, xsum_out, xsum_in, deg_out, deg_in, xi);
    k_loop_div<<<cdiv((long)NN * ED, 256), 256>>>(loop, deg_in);
    // slot 4 = PROFILED: ew1 GEMM [400k,64]@[64,256], 128x64 tile + launch_bounds(256,3)
    k_gemm<<<dim3(4, cdiv(EE, BM)), 256>>>(ea, g1we, ew, EE, ED, 256);
    k_gemm<<<dim3(4, cdiv(NN, BM)), 256>>>(loop, g1we, ew + (size_t)EE * 256, NN, ED, 256);

    k_prefix<<<1, 1024>>>(deg_in, rowptr, cursor);
    k_perm<<<cdiv(E2T, 256), 256>>>(src, dst, cursor, psrc, ipos);

    // GAT layer 1: merged xl|xr GEMM
    k_pack2<<<cdiv((long)GIN * 512, 256), 256>>>(g1wl, g1wr, wpack, GIN, 256, 256);
    k_gemm<<<dim3(8, cdiv(NN, BM)), 256>>>(xi, wpack, xlr1, NN, GIN, 512);
    k_logit_add<256, 2, 512><<<cdiv((long)E2T * 32, 256), 256>>>(xlr1, ew, g1att, src, dst, ipos, logit1);
    k_gat_reduce<256, 2, 512><<<cdiv(NN, 8), 256>>>(xlr1, logit1, rowptr, psrc, g1b, n1g, n1b, h1);

    // GAT layer 2
    k_gemm<<<dim3(2, cdiv(EE, BM)), 256>>>(ea, g2we, ew, EE, ED, HID);
    k_gemm<<<dim3(2, cdiv(NN, BM)), 256>>>(loop, g2we, ew + (size_t)EE * HID, NN, ED, HID);
    k_pack2<<<cdiv((long)HID * 256, 256), 256>>>(g2wl, g2wr, wpack, HID, HID, HID);
    k_gemm<<<dim3(4, cdiv(NN, BM)), 256>>>(h1, wpack, xlr2, NN, HID, 256);
    k_logit_add<128, 1, 256><<<cdiv((long)E2T * 32, 256), 256>>>(xlr2, ew, g2att, src, dst, ipos, logit2);
    k_gat_reduce<128, 1, 256><<<cdiv(NN, 8), 256>>>(xlr2, logit2, rowptr, psrc, g2b, n2g, n2b, h2);

    // classifier: merged pre1|pre2 GEMM + pre3 GEMM + edge pass
    k_pack2<<<cdiv((long)HID * 256, 256), 256>>>(c1w, c1w + 128 * HID, wpack, HID, HID, HID);
    k_gemm<<<dim3(4, cdiv(NN, BM)), 256>>>(h2, wpack, pre12, NN, HID, 256);
    k_gemm<<<dim3(2, cdiv(EE, BM)), 256>>>(ea, c1w + 256 * HID, ew, EE, ED, HID);
    k_cls_edge<<<592, 256>>>(pre12, ew, src, dst, c1b, c2w, c2b, c3w, c3b, out);
}

// round 14
// speedup vs baseline: 1.3609x; 1.1037x over previous
#include <cuda_runtime.h>
#include <math.h>
#include <float.h>

#define NN 50000
#define EE 400000
#define E2T (EE + NN)
#define ND 128
#define ED 64
#define HID 128
#define GIN 258
#define CIN 320

typedef unsigned long long ull;

// ---------------- packed f32x2 helpers ----------------
__device__ __forceinline__ ull pk2(float lo, float hi) {
    ull r; asm("mov.b64 %0,{%1,%2};" : "=l"(r) : "f"(lo), "f"(hi)); return r;
}
__device__ __forceinline__ ull dup2(float v) { return pk2(v, v); }
__device__ __forceinline__ void upk2(ull p, float& lo, float& hi) {
    asm("mov.b64 {%0,%1},%2;" : "=f"(lo), "=f"(hi) : "l"(p));
}
__device__ __forceinline__ ull ffma2(ull a, ull b, ull c) {
    ull d; asm("fma.rn.f32x2 %0,%1,%2,%3;" : "=l"(d) : "l"(a), "l"(b), "l"(c)); return d;
}

// ---------------- scratch ----------------
__device__ float g_xsum_out[NN * ND];
__device__ float g_xsum_in [NN * ND];
__device__ int   g_deg_out [NN];
__device__ int   g_deg_in  [NN];
__device__ float g_loop    [NN * ED];
__device__ float g_xi      [NN * GIN];
__device__ float g_xlr1    [(size_t)NN * 512];
__device__ float g_xlr2    [NN * 256];
__device__ float g_pre12   [NN * 256];
__device__ float g_wpack   [258 * 512];
__device__ float g_logit1  [E2T * 2];
__device__ float g_h1      [NN * HID];
__device__ float g_logit2  [E2T];
__device__ float g_h2      [NN * HID];
__device__ int   g_rowptr  [NN + 1];
__device__ int   g_cursor  [NN];
__device__ int   g_psrc    [E2T];
__device__ int   g_ipos    [E2T];
__device__ float g_ew      [(size_t)EE * 128];   // pre3 only now

// ---------------- stage 1+2 fused: embed + scatter + degrees + loop sums -------------
__global__ void k_embed_scatter(const int* __restrict__ src, const int* __restrict__ dst,
                                const float* __restrict__ ea,
                                const float* __restrict__ epw, const float* __restrict__ epb,
                                float* __restrict__ xsum_out, float* __restrict__ xsum_in,
                                int* __restrict__ deg_out, int* __restrict__ deg_in,
                                float* __restrict__ loop) {
    __shared__ float4 wsh[ED * 32];
    __shared__ float4 bsh4[32];
    __shared__ float  easm[16][ED];
    int tid = threadIdx.x;
    for (int i = tid; i < ED * 32; i += 256) wsh[i] = ((const float4*)epw)[i];
    if (tid < 32) bsh4[tid] = ((const float4*)epb)[tid];
    __syncthreads();
    const ulonglong2* wsh2 = (const ulonglong2*)wsh;
    int sub = tid >> 5;
    int q   = tid & 31;
    for (int base = blockIdx.x * 16; base < EE; base += gridDim.x * 16) {
        #pragma unroll
        for (int r = 0; r < 4; r++) {
            int idx = tid + r * 256;
            int ee = base + (idx >> 6);
            if (ee < EE) easm[idx >> 6][idx & 63] = ea[(size_t)ee * ED + (idx & 63)];
        }
        __syncthreads();
        {
            int e_loc = tid >> 4, q2 = tid & 15;
            int e = base + e_loc;
            if (e < EE) {
                int d = dst[e];
                if (q2 == 0) {
                    atomicAdd(&deg_in[d], 1);
                    atomicAdd(&deg_out[src[e]], 1);
                }
                float4 v = ((const float4*)easm[e_loc])[q2];
                atomicAdd((float4*)(loop + (size_t)d * ED + q2 * 4), v);
            }
        }
        int e0 = base + sub, e1 = base + sub + 8;
        float4 bb = bsh4[q];
        ull a0[2] = { pk2(bb.x, bb.y), pk2(bb.z, bb.w) };
        ull a1[2] = { a0[0], a0[1] };
        const float* er0 = easm[sub];
        const float* er1 = easm[sub + 8];
        #pragma unroll
        for (int k = 0; k < ED; k++) {
            ulonglong2 w2 = wsh2[k * 32 + q];
            ull b0 = dup2(er0[k]), b1 = dup2(er1[k]);
            a0[0] = ffma2(b0, w2.x, a0[0]); a0[1] = ffma2(b0, w2.y, a0[1]);
            a1[0] = ffma2(b1, w2.x, a1[0]); a1[1] = ffma2(b1, w2.y, a1[1]);
        }
        if (e0 < EE) {
            float4 o; upk2(a0[0], o.x, o.y); upk2(a0[1], o.z, o.w);
            o.x = fmaxf(o.x, 0.f); o.y = fmaxf(o.y, 0.f); o.z = fmaxf(o.z, 0.f); o.w = fmaxf(o.w, 0.f);
            int s = src[e0], d = dst[e0];
            atomicAdd((float4*)(xsum_out + (size_t)s * ND + q * 4), o);
            atomicAdd((float4*)(xsum_in  + (size_t)d * ND + q * 4), o);
        }
        if (e1 < EE) {
            float4 o; upk2(a1[0], o.x, o.y); upk2(a1[1], o.z, o.w);
            o.x = fmaxf(o.x, 0.f); o.y = fmaxf(o.y, 0.f); o.z = fmaxf(o.z, 0.f); o.w = fmaxf(o.w, 0.f);
            int s = src[e1], d = dst[e1];
            atomicAdd((float4*)(xsum_out + (size_t)s * ND + q * 4), o);
            atomicAdd((float4*)(xsum_in  + (size_t)d * ND + q * 4), o);
        }
        __syncthreads();
    }
}

// ---------------- stage 3 ----------------
__global__ void k_build_xi(const float* __restrict__ node_stats,
                           const float* __restrict__ xsum_out, const float* __restrict__ xsum_in,
                           const int* __restrict__ deg_out, const int* __restrict__ deg_in,
                           float* __restrict__ xi) {
    int tid = blockIdx.x * blockDim.x + threadIdx.x;
    if (tid >= NN * GIN) return;
    int i = tid / GIN, j = tid - i * GIN;
    float v;
    if (j < 128)      v = xsum_out[i * 128 + j]        / fmaxf((float)deg_out[i], 1.f);
    else if (j < 256) v = xsum_in [i * 128 + (j - 128)] / fmaxf((float)deg_in [i], 1.f);
    else              v = node_stats[i * 2 + (j - 256)];
    xi[tid] = v;
}

__global__ void k_loop_div(float* __restrict__ loop, const int* __restrict__ deg_in) {
    int tid = blockIdx.x * blockDim.x + threadIdx.x;
    if (tid >= NN * ED) return;
    int i = tid >> 6;
    loop[tid] = loop[tid] / fmaxf((float)deg_in[i], 1.f);
}

// ---------------- CSR prefix scan ----------------
__global__ void k_prefix(const int* __restrict__ deg_in, int* __restrict__ rowptr,
                         int* __restrict__ cursor) {
    __shared__ int wsums[32];
    __shared__ int carry_s;
    int t = threadIdx.x, lane = t & 31, wid = t >> 5;
    if (t == 0) carry_s = 0;
    __syncthreads();
    for (int base = 0; base < NN; base += 1024) {
        int n = base + t;
        int v = (n < NN) ? deg_in[n] + 1 : 0;
        int x = v;
        #pragma unroll
        for (int o = 1; o < 32; o <<= 1) {
            int y = __shfl_up_sync(0xffffffffu, x, o);
            if (lane >= o) x += y;
        }
        if (lane == 31) wsums[wid] = x;
        __syncthreads();
        if (wid == 0) {
            int s = wsums[lane];
            #pragma unroll
            for (int o = 1; o < 32; o <<= 1) {
                int y = __shfl_up_sync(0xffffffffu, s, o);
                if (lane >= o) s += y;
            }
            wsums[lane] = s;
        }
        __syncthreads();
        int excl = x - v + (wid > 0 ? wsums[wid - 1] : 0) + carry_s;
        if (n < NN) { rowptr[n] = excl; cursor[n] = excl; }
        __syncthreads();
        if (t == 0) carry_s += wsums[31];
        __syncthreads();
    }
    if (t == 0) rowptr[NN] = E2T;
}

__global__ void k_perm(const int* __restrict__ src, const int* __restrict__ dst,
                       int* __restrict__ cursor, int* __restrict__ psrc,
                       int* __restrict__ ipos) {
    int e = blockIdx.x * blockDim.x + threadIdx.x;
    if (e < EE) {
        int pos = atomicAdd(&cursor[dst[e]], 1);
        psrc[pos] = src[e];
        ipos[e] = pos;
    } else if (e < E2T) {
        int i = e - EE;
        int pos = atomicAdd(&cursor[i], 1);
        psrc[pos] = i;
        ipos[e] = pos;
    }
}

// ---------------- weight pack ----------------
__global__ void k_pack2(const float* __restrict__ B1, const float* __restrict__ B2,
                        float* __restrict__ C, int K, int N1, int N2) {
    int i = blockIdx.x * 256 + threadIdx.x;
    int N = N1 + N2;
    if (i >= K * N) return;
    int k = i / N, c = i - k * N;
    C[i] = (c < N1) ? B1[k * N1 + c] : B2[k * N2 + (c - N1)];
}

// ---------------- fp32 tiled GEMM (128x64 tile, 8x4/thread) ----------------
#define BM 128
#define BN 64
#define BKK 16
__global__ void __launch_bounds__(256, 3)
k_gemm(const float* __restrict__ A, const float* __restrict__ B,
       float* __restrict__ C, int M, int K, int Nc) {
    __shared__ float As[BKK][BM + 4];
    __shared__ float Bs[BKK][BN + 4];
    int brow = blockIdx.y * BM, bcol = blockIdx.x * BN;
    int tid = threadIdx.x;
    int tr = tid >> 4, tc = tid & 15;
    ull acc[8][2];
    #pragma unroll
    for (int i = 0; i < 8; i++) { acc[i][0] = 0ull; acc[i][1] = 0ull; }
    for (int k0 = 0; k0 < K; k0 += BKK) {
        #pragma unroll
        for (int it = 0; it < 4; it++) {
            int idx = tid + it * 256;
            int r = idx >> 3, c2 = idx & 7;
            int gr = brow + r, gc = k0 + c2 * 2;
            float2 v = make_float2(0.f, 0.f);
            if (gr < M) {
                if (gc + 1 < K)  v = *(const float2*)&A[(size_t)gr * K + gc];
                else if (gc < K) v.x = A[(size_t)gr * K + gc];
            }
            As[c2 * 2][r] = v.x;
            As[c2 * 2 + 1][r] = v.y;
        }
        {
            int r = tid >> 4, c4 = tid & 15;
            int gr = k0 + r;
            float4 v = make_float4(0.f, 0.f, 0.f, 0.f);
            if (gr < K) v = *(const float4*)&B[(size_t)gr * Nc + bcol + c4 * 4];
            *(float4*)&Bs[r][c4 * 4] = v;
        }
        __syncthreads();
        #pragma unroll
        for (int kk = 0; kk < BKK; kk++) {
            float4 a0 = *(const float4*)&As[kk][tr * 8];
            float4 a1 = *(const float4*)&As[kk][tr * 8 + 4];
            ulonglong2 b2 = *(const ulonglong2*)&Bs[kk][tc * 4];
            ull d;
            d = dup2(a0.x); acc[0][0] = ffma2(d, b2.x, acc[0][0]); acc[0][1] = ffma2(d, b2.y, acc[0][1]);
            d = dup2(a0.y); acc[1][0] = ffma2(d, b2.x, acc[1][0]); acc[1][1] = ffma2(d, b2.y, acc[1][1]);
            d = dup2(a0.z); acc[2][0] = ffma2(d, b2.x, acc[2][0]); acc[2][1] = ffma2(d, b2.y, acc[2][1]);
            d = dup2(a0.w); acc[3][0] = ffma2(d, b2.x, acc[3][0]); acc[3][1] = ffma2(d, b2.y, acc[3][1]);
            d = dup2(a1.x); acc[4][0] = ffma2(d, b2.x, acc[4][0]); acc[4][1] = ffma2(d, b2.y, acc[4][1]);
            d = dup2(a1.y); acc[5][0] = ffma2(d, b2.x, acc[5][0]); acc[5][1] = ffma2(d, b2.y, acc[5][1]);
            d = dup2(a1.z); acc[6][0] = ffma2(d, b2.x, acc[6][0]); acc[6][1] = ffma2(d, b2.y, acc[6][1]);
            d = dup2(a1.w); acc[7][0] = ffma2(d, b2.x, acc[7][0]); acc[7][1] = ffma2(d, b2.y, acc[7][1]);
        }
        __syncthreads();
    }
    #pragma unroll
    for (int i = 0; i < 8; i++) {
        int row = brow + tr * 8 + i;
        if (row >= M) continue;
        float v[4];
        upk2(acc[i][0], v[0], v[1]); upk2(acc[i][1], v[2], v[3]);
        #pragma unroll
        for (int j = 0; j < 4; j++) {
            int col = bcol + tc * 4 + j;
            if (col < Nc) C[(size_t)row * Nc + col] = v[j];
        }
    }
}

// ---------------- fused GEMM + logit epilogue: ew never materialized --------------
// A: [M,64] (ea rows or loop rows); B: we [64,OUT]. Epilogue computes partial
// logits: sum over this block's 64 cols of att*leaky(xl+xr+ew) -> atomicAdd.
template <int OUT, int H, bool IS_LOOP>
__global__ void __launch_bounds__(256, 3)
k_gemm_logit(const float* __restrict__ A, const float* __restrict__ B, int M,
             const float* __restrict__ xlr, const float* __restrict__ att,
             const int* __restrict__ src, const int* __restrict__ dst,
             const int* __restrict__ ipos, float* __restrict__ logit) {
    const int STRIDE = 2 * OUT;
    __shared__ float As[BKK][BM + 4];
    __shared__ float Bs[BKK][BN + 4];
    __shared__ int   ses[BM], des[BM], pss[BM];
    __shared__ float atts[BN];
    int brow = blockIdx.y * BM, bcol = blockIdx.x * BN;
    int tid = threadIdx.x;
    int tr = tid >> 4, tc = tid & 15;
    if (tid < BM) {
        int row = brow + tid;
        if (row < M) {
            if (IS_LOOP) { ses[tid] = row; des[tid] = row; pss[tid] = ipos[EE + row]; }
            else         { ses[tid] = src[row]; des[tid] = dst[row]; pss[tid] = ipos[row]; }
        }
    }
    if (tid >= 128 && tid < 128 + BN) atts[tid - 128] = att[bcol + tid - 128];
    ull acc[8][2];
    #pragma unroll
    for (int i = 0; i < 8; i++) { acc[i][0] = 0ull; acc[i][1] = 0ull; }
    for (int k0 = 0; k0 < ED; k0 += BKK) {
        #pragma unroll
        for (int it = 0; it < 4; it++) {
            int idx = tid + it * 256;
            int r = idx >> 3, c2 = idx & 7;
            int gr = brow + r, gc = k0 + c2 * 2;
            float2 v = make_float2(0.f, 0.f);
            if (gr < M) v = *(const float2*)&A[(size_t)gr * ED + gc];
            As[c2 * 2][r] = v.x;
            As[c2 * 2 + 1][r] = v.y;
        }
        {
            int r = tid >> 4, c4 = tid & 15;
            int gr = k0 + r;
            float4 v = *(const float4*)&B[(size_t)gr * OUT + bcol + c4 * 4];
            *(float4*)&Bs[r][c4 * 4] = v;
        }
        __syncthreads();
        #pragma unroll
        for (int kk = 0; kk < BKK; kk++) {
            float4 a0 = *(const float4*)&As[kk][tr * 8];
            float4 a1 = *(const float4*)&As[kk][tr * 8 + 4];
            ulonglong2 b2 = *(const ulonglong2*)&Bs[kk][tc * 4];
            ull d;
            d = dup2(a0.x); acc[0][0] = ffma2(d, b2.x, acc[0][0]); acc[0][1] = ffma2(d, b2.y, acc[0][1]);
            d = dup2(a0.y); acc[1][0] = ffma2(d, b2.x, acc[1][0]); acc[1][1] = ffma2(d, b2.y, acc[1][1]);
            d = dup2(a0.z); acc[2][0] = ffma2(d, b2.x, acc[2][0]); acc[2][1] = ffma2(d, b2.y, acc[2][1]);
            d = dup2(a0.w); acc[3][0] = ffma2(d, b2.x, acc[3][0]); acc[3][1] = ffma2(d, b2.y, acc[3][1]);
            d = dup2(a1.x); acc[4][0] = ffma2(d, b2.x, acc[4][0]); acc[4][1] = ffma2(d, b2.y, acc[4][1]);
            d = dup2(a1.y); acc[5][0] = ffma2(d, b2.x, acc[5][0]); acc[5][1] = ffma2(d, b2.y, acc[5][1]);
            d = dup2(a1.z); acc[6][0] = ffma2(d, b2.x, acc[6][0]); acc[6][1] = ffma2(d, b2.y, acc[6][1]);
            d = dup2(a1.w); acc[7][0] = ffma2(d, b2.x, acc[7][0]); acc[7][1] = ffma2(d, b2.y, acc[7][1]);
        }
        __syncthreads();
    }
    // epilogue: partial logit for this 64-col tile
    int h = (H == 2) ? (bcol >> 7) : 0;
    int gcol = bcol + tc * 4;
    float4 at = *(const float4*)&atts[tc * 4];
    int lane = tid & 31;
    #pragma unroll
    for (int i = 0; i < 8; i++) {
        int r = tr * 8 + i;
        int row = brow + r;
        float p = 0.f;
        if (row < M) {
            int s = ses[r], d = des[r];
            float4 xlv = *(const float4*)(xlr + (size_t)s * STRIDE + gcol);
            float4 xrv = *(const float4*)(xlr + (size_t)d * STRIDE + OUT + gcol);
            float a[4];
            upk2(acc[i][0], a[0], a[1]); upk2(acc[i][1], a[2], a[3]);
            float v;
            v = a[0] + xlv.x + xrv.x; v = v > 0.f ? v : 0.2f * v; p = fmaf(v, at.x, p);
            v = a[1] + xlv.y + xrv.y; v = v > 0.f ? v : 0.2f * v; p = fmaf(v, at.y, p);
            v = a[2] + xlv.z + xrv.z; v = v > 0.f ? v : 0.2f * v; p = fmaf(v, at.z, p);
            v = a[3] + xlv.w + xrv.w; v = v > 0.f ? v : 0.2f * v; p = fmaf(v, at.w, p);
        }
        #pragma unroll
        for (int o = 1; o < 16; o <<= 1) p += __shfl_xor_sync(0xffffffffu, p, o);
        if ((lane & 15) == 0 && row < M)
            atomicAdd(&logit[(size_t)pss[r] * H + h], p);
    }
}

// ---------------- GATv2 fused reduce ----------------
template <int OUT, int H, int STRIDE>
__global__ void __launch_bounds__(256)
k_gat_reduce(const float* __restrict__ xl, const float* __restrict__ slog,
             const int* __restrict__ rowptr, const int* __restrict__ psrc,
             const float* __restrict__ bias, const float* __restrict__ gg,
             const float* __restrict__ bb, float* __restrict__ out) {
    const int R = OUT / 32;
    __shared__ float csm[8][32 * H];
    __shared__ int   ssm2[8][32];
    int warp = threadIdx.x >> 5, lane = threadIdx.x & 31;
    int node = blockIdx.x * 8 + warp;
    if (node >= NN) return;
    int r0 = rowptr[node], r1 = rowptr[node + 1], cnt = r1 - r0;
    float mx[H];
    #pragma unroll
    for (int h = 0; h < H; h++) mx[h] = -FLT_MAX;
    for (int j = lane; j < cnt; j += 32) {
        #pragma unroll
        for (int h = 0; h < H; h++) mx[h] = fmaxf(mx[h], slog[(size_t)(r0 + j) * H + h]);
    }
    #pragma unroll
    for (int h = 0; h < H; h++)
        #pragma unroll
        for (int o = 16; o; o >>= 1) mx[h] = fmaxf(mx[h], __shfl_xor_sync(0xffffffffu, mx[h], o));
    float den[H];
    #pragma unroll
    for (int h = 0; h < H; h++) den[h] = 0.f;
    for (int j = lane; j < cnt; j += 32) {
        #pragma unroll
        for (int h = 0; h < H; h++) den[h] += expf(slog[(size_t)(r0 + j) * H + h] - mx[h]);
    }
    float inv[H];
    #pragma unroll
    for (int h = 0; h < H; h++) {
        #pragma unroll
        for (int o = 16; o; o >>= 1) den[h] += __shfl_xor_sync(0xffffffffu, den[h], o);
        inv[h] = 1.f / fmaxf(den[h], 1e-16f);
    }
    float acc[R];
    #pragma unroll
    for (int j = 0; j < R; j++) acc[j] = 0.f;
    for (int j0 = 0; j0 < cnt; j0 += 32) {
        int jj = j0 + lane;
        if (jj < cnt) {
            ssm2[warp][lane] = psrc[r0 + jj];
            #pragma unroll
            for (int h = 0; h < H; h++)
                csm[warp][lane * H + h] = expf(slog[(size_t)(r0 + jj) * H + h] - mx[h]) * inv[h];
        }
        __syncwarp();
        int lim = min(32, cnt - j0);
        for (int k = 0; k < lim; k++) {
            int s = ssm2[warp][k];
            const float* row = xl + (size_t)s * STRIDE;
            if (H == 2) {
                float c0 = csm[warp][k * 2], c1 = csm[warp][k * 2 + 1];
                #pragma unroll
                for (int j = 0; j < R; j++)
                    acc[j] = fmaf((j < R / 2) ? c0 : c1, row[j * 32 + lane], acc[j]);
            } else {
                float c0 = csm[warp][k];
                #pragma unroll
                for (int j = 0; j < R; j++)
                    acc[j] = fmaf(c0, row[j * 32 + lane], acc[j]);
            }
        }
        __syncwarp();
    }
    float v[4];
    #pragma unroll
    for (int j = 0; j < 4; j++) {
        if (H == 2) v[j] = 0.5f * (acc[j] + acc[j + 4]) + bias[j * 32 + lane];
        else        v[j] = acc[j] + bias[j * 32 + lane];
    }
    float s = v[0] + v[1] + v[2] + v[3];
    #pragma unroll
    for (int o = 16; o; o >>= 1) s += __shfl_xor_sync(0xffffffffu, s, o);
    float mu = s * (1.f / 128.f);
    float sq = 0.f;
    #pragma unroll
    for (int j = 0; j < 4; j++) { v[j] -= mu; sq = fmaf(v[j], v[j], sq); }
    #pragma unroll
    for (int o = 16; o; o >>= 1) sq += __shfl_xor_sync(0xffffffffu, sq, o);
    float is = rsqrtf(sq * (1.f / 128.f) + 1e-5f);
    #pragma unroll
    for (int j = 0; j < 4; j++) {
        int oi = j * 32 + lane;
        float o2 = v[j] * is * gg[oi] + bb[oi];
        out[(size_t)node * 128 + oi] = o2 > 0.f ? o2 : (expf(o2) - 1.f);
    }
}

// ---------------- classifier edge pass ----------------
__global__ void __launch_bounds__(256)
k_cls_edge(const float* __restrict__ pre12, const float* __restrict__ pre3,
           const int* __restrict__ src, const int* __restrict__ dst,
           const float* __restrict__ c1b, const float* __restrict__ c2w,
           const float* __restrict__ c2b, const float* __restrict__ c3w,
           const float* __restrict__ c3b, float* __restrict__ out) {
    __shared__ float c2s[HID * 64];
    __shared__ float hb[8][HID];
    __shared__ float b1s[HID];
    __shared__ float b2s[64];
    __shared__ float c3s[64];
    int tid = threadIdx.x;
    for (int i = tid; i < HID * 64; i += 256) c2s[i] = c2w[i];
    if (tid < HID) b1s[tid] = c1b[tid];
    if (tid < 64)  { b2s[tid] = c2b[tid]; c3s[tid] = c3w[tid]; }
    __syncthreads();
    const ull* c2p = (const ull*)c2s;
    float c3bv = c3b[0];
    int warp = tid >> 5, lane = tid & 31;
    float* h1r = hb[warp];
    const int stride = gridDim.x * 8;
    for (int e = blockIdx.x * 8 + warp; e < EE; e += stride) {
        int s = src[e], d = dst[e];
        float4 p1 = *(const float4*)(pre12 + (size_t)s * 256 + lane * 4);
        float4 p2 = *(const float4*)(pre12 + (size_t)d * 256 + 128 + lane * 4);
        float4 p3 = *(const float4*)(pre3 + (size_t)e * HID + lane * 4);
        float4 bb = ((const float4*)b1s)[lane];
        float4 h;
        h.x = fmaxf(p1.x + p2.x + p3.x + bb.x, 0.f);
        h.y = fmaxf(p1.y + p2.y + p3.y + bb.y, 0.f);
        h.z = fmaxf(p1.z + p2.z + p3.z + bb.z, 0.f);
        h.w = fmaxf(p1.w + p2.w + p3.w + bb.w, 0.f);
        __syncwarp();
        ((float4*)h1r)[lane] = h;
        __syncwarp();
        ull acc = pk2(b2s[lane * 2], b2s[lane * 2 + 1]);
        #pragma unroll 8
        for (int k = 0; k < HID; k++)
            acc = ffma2(dup2(h1r[k]), c2p[k * 32 + lane], acc);
        float x, y; upk2(acc, x, y);
        float v = fmaxf(x, 0.f) * c3s[lane * 2] + fmaxf(y, 0.f) * c3s[lane * 2 + 1];
        #pragma unroll
        for (int o = 16; o; o >>= 1) v += __shfl_xor_sync(0xffffffffu, v, o);
        if (lane == 0) out[e] = v + c3bv;
    }
}

// ---------------- launch ----------------
static inline int cdiv(long a, long b) { return (int)((a + b - 1) / b); }

extern "C" void kernel_launch(void* const* d_in, const int* in_sizes, int n_in,
                              void* d_out, int out_size) {
    const float* node_stats = (const float*)d_in[1];
    const int*   ei   = (const int*)d_in[2];
    const int*   src  = ei;
    const int*   dst  = ei + EE;
    const float* ea   = (const float*)d_in[3];
    const float* epw  = (const float*)d_in[4];
    const float* epb  = (const float*)d_in[5];
    const float* g1wl = (const float*)d_in[6];
    const float* g1wr = (const float*)d_in[7];
    const float* g1we = (const float*)d_in[8];
    const float* g1att= (const float*)d_in[9];
    const float* g1b  = (const float*)d_in[10];
    const float* n1g  = (const float*)d_in[11];
    const float* n1b  = (const float*)d_in[12];
    const float* g2wl = (const float*)d_in[13];
    const float* g2wr = (const float*)d_in[14];
    const float* g2we = (const float*)d_in[15];
    const float* g2att= (const float*)d_in[16];
    const float* g2b  = (const float*)d_in[17];
    const float* n2g  = (const float*)d_in[18];
    const float* n2b  = (const float*)d_in[19];
    const float* c1w  = (const float*)d_in[20];
    const float* c1b  = (const float*)d_in[21];
    const float* c2w  = (const float*)d_in[22];
    const float* c2b  = (const float*)d_in[23];
    const float* c3w  = (const float*)d_in[24];
    const float* c3b  = (const float*)d_in[25];
    float* out = (float*)d_out;

    float *xsum_out, *xsum_in, *loop, *xi, *xlr1, *xlr2, *pre12, *wpack;
    float *logit1, *h1, *logit2, *h2, *ew;
    int *deg_out, *deg_in, *rowptr, *cursor, *psrc, *ipos;
    cudaGetSymbolAddress((void**)&xsum_out, g_xsum_out);
    cudaGetSymbolAddress((void**)&xsum_in,  g_xsum_in);
    cudaGetSymbolAddress((void**)&deg_out,  g_deg_out);
    cudaGetSymbolAddress((void**)&deg_in,   g_deg_in);
    cudaGetSymbolAddress((void**)&loop,     g_loop);
    cudaGetSymbolAddress((void**)&xi,       g_xi);
    cudaGetSymbolAddress((void**)&xlr1,     g_xlr1);
    cudaGetSymbolAddress((void**)&xlr2,     g_xlr2);
    cudaGetSymbolAddress((void**)&pre12,    g_pre12);
    cudaGetSymbolAddress((void**)&wpack,    g_wpack);
    cudaGetSymbolAddress((void**)&logit1,   g_logit1);
    cudaGetSymbolAddress((void**)&h1,       g_h1);
    cudaGetSymbolAddress((void**)&logit2,   g_logit2);
    cudaGetSymbolAddress((void**)&h2,       g_h2);
    cudaGetSymbolAddress((void**)&rowptr,   g_rowptr);
    cudaGetSymbolAddress((void**)&cursor,   g_cursor);
    cudaGetSymbolAddress((void**)&psrc,     g_psrc);
    cudaGetSymbolAddress((void**)&ipos,     g_ipos);
    cudaGetSymbolAddress((void**)&ew,       g_ew);

    cudaMemsetAsync(xsum_out, 0, sizeof(float) * NN * ND);
    cudaMemsetAsync(xsum_in,  0, sizeof(float) * NN * ND);
    cudaMemsetAsync(deg_out,  0, sizeof(int) * NN);
    cudaMemsetAsync(deg_in,   0, sizeof(int) * NN);
    cudaMemsetAsync(loop,     0, sizeof(float) * NN * ED);
    cudaMemsetAsync(logit1,   0, sizeof(float) * E2T * 2);
    cudaMemsetAsync(logit2,   0, sizeof(float) * E2T);

    // slot 1..3: embed, build_xi, pack2 | slot 4 = PROFILED: xlr1 merged GEMM
    k_embed_scatter<<<2048, 256>>>(src, dst, ea, epw, epb, xsum_out, xsum_in,
                                   deg_out, deg_in, loop);
    k_build_xi<<<cdiv((long)NN * GIN, 256), 256>>>(node_stats, xsum_out, xsum_in, deg_out, deg_in, xi);
    k_pack2<<<cdiv((long)GIN * 512, 256), 256>>>(g1wl, g1wr, wpack, GIN, 256, 256);
    k_gemm<<<dim3(8, cdiv(NN, BM)), 256>>>(xi, wpack, xlr1, NN, GIN, 512);

    k_loop_div<<<cdiv((long)NN * ED, 256), 256>>>(loop, deg_in);
    k_prefix<<<1, 1024>>>(deg_in, rowptr, cursor);
    k_perm<<<cdiv(E2T, 256), 256>>>(src, dst, cursor, psrc, ipos);

    // GAT layer 1: fused ew-GEMM + logit epilogue (edges + self-loops)
    k_gemm_logit<256, 2, false><<<dim3(4, cdiv(EE, BM)), 256>>>(
        ea, g1we, EE, xlr1, g1att, src, dst, ipos, logit1);
    k_gemm_logit<256, 2, true><<<dim3(4, cdiv(NN, BM)), 256>>>(
        loop, g1we, NN, xlr1, g1att, src, dst, ipos, logit1);
    k_gat_reduce<256, 2, 512><<<cdiv(NN, 8), 256>>>(xlr1, logit1, rowptr, psrc, g1b, n1g, n1b, h1);

    // GAT layer 2
    k_pack2<<<cdiv((long)HID * 256, 256), 256>>>(g2wl, g2wr, wpack, HID, HID, HID);
    k_gemm<<<dim3(4, cdiv(NN, BM)), 256>>>(h1, wpack, xlr2, NN, HID, 256);
    k_gemm_logit<128, 1, false><<<dim3(2, cdiv(EE, BM)), 256>>>(
        ea, g2we, EE, xlr2, g2att, src, dst, ipos, logit2);
    k_gemm_logit<128, 1, true><<<dim3(2, cdiv(NN, BM)), 256>>>(
        loop, g2we, NN, xlr2, g2att, src, dst, ipos, logit2);
    k_gat_reduce<128, 1, 256><<<cdiv(NN, 8), 256>>>(xlr2, logit2, rowptr, psrc, g2b, n2g, n2b, h2);

    // classifier
    k_pack2<<<cdiv((long)HID * 256, 256), 256>>>(c1w, c1w + 128 * HID, wpack, HID, HID, HID);
    k_gemm<<<dim3(4, cdiv(NN, BM)), 256>>>(h2, wpack, pre12, NN, HID, 256);
    k_gemm<<<dim3(2, cdiv(EE, BM)), 256>>>(ea, c1w + 256 * HID, ew, EE, ED, HID);
    k_cls_edge<<<592, 256>>>(pre12, ew, src, dst, c1b, c2w, c2b, c3w, c3b, out);
}